// round 4
// baseline (speedup 1.0000x reference)
#include <cuda_runtime.h>
#include <cstdint>
#include <cstddef>

#define NN 50000
#define NE 800000

// ---------------- static scratch (no allocs allowed) ----------------
__device__ float g_EP1[(size_t)NN * 128];    // [n][2c] = (E,P) c<64
__device__ float g_aggr1[(size_t)NN * 64];
__device__ float g_buf1[(size_t)NN * 256];   // out1 -> h1 (in-place norm+relu)
__device__ float g_EP2[(size_t)NN * 512];    // [n][2c] c<256
__device__ float g_aggr2[(size_t)NN * 256];
__device__ float g_buf2[(size_t)NN * 128];   // out2 -> h2
__device__ int   g_counts[NN];
__device__ int   g_off[NN + 1];
__device__ int   g_cur[NN];
__device__ int   g_srcs[NE];
__device__ float g_pool[4 * 128];

// ---------------- f32x2 helpers (Blackwell packed fp32) ----------------
__device__ __forceinline__ unsigned long long dup2(float a) {
    unsigned long long r; unsigned int u = __float_as_uint(a);
    asm("mov.b64 %0, {%1, %1};" : "=l"(r) : "r"(u));
    return r;
}
__device__ __forceinline__ unsigned long long fma2(unsigned long long a,
                                                   unsigned long long b,
                                                   unsigned long long c) {
    unsigned long long d;
    asm("fma.rn.f32x2 %0, %1, %2, %3;" : "=l"(d) : "l"(a), "l"(b), "l"(c));
    return d;
}
__device__ __forceinline__ float2 unpk2(unsigned long long v) {
    unsigned int lo, hi;
    asm("mov.b64 {%0, %1}, %2;" : "=r"(lo), "=r"(hi) : "l"(v));
    return make_float2(__uint_as_float(lo), __uint_as_float(hi));
}

// ---------------- CSR build ----------------
__global__ void zero_k(int n) {
    int i = blockIdx.x * 256 + threadIdx.x;
    if (i < n) g_counts[i] = 0;
    if (i < 512) g_pool[i] = 0.0f;
}

__global__ void count_k(const int* __restrict__ ei, int E) {
    int i = blockIdx.x * 256 + threadIdx.x;
    if (i >= E) return;
    atomicAdd(&g_counts[ei[E + i]], 1);
}

__global__ void scan_k(int n) {
    __shared__ int s[1024];
    __shared__ int carry;
    int t = threadIdx.x;
    if (t == 0) { carry = 0; g_off[0] = 0; g_cur[0] = 0; }
    __syncthreads();
    for (int base = 0; base < n; base += 1024) {
        int i = base + t;
        int v = (i < n) ? g_counts[i] : 0;
        s[t] = v;
        __syncthreads();
        for (int o = 1; o < 1024; o <<= 1) {
            int a = (t >= o) ? s[t - o] : 0;
            __syncthreads();
            s[t] += a;
            __syncthreads();
        }
        int incl = s[t] + carry;
        if (i < n) {
            g_off[i + 1] = incl;
            if (i + 1 < n) g_cur[i + 1] = incl;
        }
        __syncthreads();
        if (t == 0) carry += s[1023];
        __syncthreads();
    }
}

__global__ void scatter_k(const int* __restrict__ ei, int E) {
    int i = blockIdx.x * 256 + threadIdx.x;
    if (i >= E) return;
    int s = ei[i], d = ei[E + i];
    int pos = atomicAdd(&g_cur[d], 1);
    g_srcs[pos] = s;
}

// ---------------- generic SIMT GEMM body, f32x2 inner loop ----------------
// C[M,N] = A[M,K]@W[K,N] (+ A2[M,K2]@W2[K2,N]) + bias
// EPI=0: raw+bias. EPI=1: v=relu(acc+bias); write EP pairs (e, e*v), e=exp(v*t).
// BM=BN=64, BK=16, 256 threads, 4x4 per thread. N multiple of 64, K multiple of 16.
template <int EPI, int K1, int K2, int N, bool HAS2>
__device__ __forceinline__ void gemm_body(
    const float* __restrict__ A, const float* __restrict__ W,
    const float* __restrict__ A2, const float* __restrict__ W2,
    const float* __restrict__ bias, const float* __restrict__ tv,
    float* __restrict__ out, int M)
{
    __shared__ float As[16][64];
    __shared__ float Bs[16][64];
    int t = threadIdx.x;
    int m0 = blockIdx.y * 64, n0 = blockIdx.x * 64;
    int lm = t >> 2, lk4 = (t & 3) * 4;   // A-tile load map
    int bk = t >> 4, bn4 = (t & 15) * 4;  // B-tile load map
    int tx = t & 15, ty = t >> 4;

    unsigned long long acc[4][2];
#pragma unroll
    for (int i = 0; i < 4; i++) { acc[i][0] = 0ull; acc[i][1] = 0ull; }

#pragma unroll 1
    for (int phase = 0; phase < (HAS2 ? 2 : 1); ++phase) {
        const float* Ap = phase ? A2 : A;
        const float* Wp = phase ? W2 : W;
        const int Kp = phase ? K2 : K1;
        const int nt = Kp / 16;
#pragma unroll 1
        for (int kt = 0; kt < nt; ++kt) {
            int kb = kt * 16;
            float4 av4 = make_float4(0.f, 0.f, 0.f, 0.f);
            int arow = m0 + lm;
            if (arow < M) av4 = *(const float4*)(Ap + (size_t)arow * Kp + kb + lk4);
            float4 bv4 = *(const float4*)(Wp + (size_t)(kb + bk) * N + n0 + bn4);
            __syncthreads();  // previous compute done before smem overwrite
            As[lk4 + 0][lm] = av4.x;
            As[lk4 + 1][lm] = av4.y;
            As[lk4 + 2][lm] = av4.z;
            As[lk4 + 3][lm] = av4.w;
            *(float4*)&Bs[bk][bn4] = bv4;
            __syncthreads();
#pragma unroll
            for (int k = 0; k < 16; k++) {
                float4 a = *(const float4*)&As[k][ty * 4];
                ulonglong2 b = *(const ulonglong2*)&Bs[k][tx * 4];
                unsigned long long a0 = dup2(a.x), a1 = dup2(a.y),
                                   a2 = dup2(a.z), a3 = dup2(a.w);
                acc[0][0] = fma2(a0, b.x, acc[0][0]);
                acc[0][1] = fma2(a0, b.y, acc[0][1]);
                acc[1][0] = fma2(a1, b.x, acc[1][0]);
                acc[1][1] = fma2(a1, b.y, acc[1][1]);
                acc[2][0] = fma2(a2, b.x, acc[2][0]);
                acc[2][1] = fma2(a2, b.y, acc[2][1]);
                acc[3][0] = fma2(a3, b.x, acc[3][0]);
                acc[3][1] = fma2(a3, b.y, acc[3][1]);
            }
        }
    }

    int gn0 = n0 + tx * 4;
#pragma unroll
    for (int i = 0; i < 4; i++) {
        int row = m0 + ty * 4 + i;
        if (row >= M) continue;
        float2 c0 = unpk2(acc[i][0]);
        float2 c1 = unpk2(acc[i][1]);
        float v[4] = {c0.x, c0.y, c1.x, c1.y};
        if (EPI == 0) {
            float4 o;
            o.x = v[0] + bias[gn0 + 0];
            o.y = v[1] + bias[gn0 + 1];
            o.z = v[2] + bias[gn0 + 2];
            o.w = v[3] + bias[gn0 + 3];
            *(float4*)(out + (size_t)row * N + gn0) = o;
        } else {
            float e[4], p[4];
#pragma unroll
            for (int j = 0; j < 4; j++) {
                float vv = fmaxf(v[j] + bias[gn0 + j], 0.0f);
                e[j] = __expf(vv * tv[gn0 + j]);
                p[j] = e[j] * vv;
            }
            float* base = out + (size_t)row * (2 * N) + 2 * gn0;
            *(float4*)(base)     = make_float4(e[0], p[0], e[1], p[1]);
            *(float4*)(base + 4) = make_float4(e[2], p[2], e[3], p[3]);
        }
    }
}

// ---- GEMM wrapper kernels (reference device globals directly; no symbol queries) ----
__global__ __launch_bounds__(256) void gemm_ep1_k(
    const float* __restrict__ x, const float* __restrict__ w,
    const float* __restrict__ b, const float* __restrict__ tv, int M)
{
    gemm_body<1, 64, 0, 64, false>(x, w, nullptr, nullptr, b, tv, g_EP1, M);
}
__global__ __launch_bounds__(256) void gemm_l1_k(
    const float* __restrict__ x, const float* __restrict__ wl,
    const float* __restrict__ bl, const float* __restrict__ wr, int M)
{
    gemm_body<0, 64, 64, 256, true>(g_aggr1, wl, x, wr, bl, nullptr, g_buf1, M);
}
__global__ __launch_bounds__(256) void gemm_ep2_k(
    const float* __restrict__ w, const float* __restrict__ b,
    const float* __restrict__ tv, int M)
{
    gemm_body<1, 256, 0, 256, false>(g_buf1, w, nullptr, nullptr, b, tv, g_EP2, M);
}
__global__ __launch_bounds__(256) void gemm_l2_k(
    const float* __restrict__ wl, const float* __restrict__ bl,
    const float* __restrict__ wr, int M)
{
    gemm_body<0, 256, 256, 128, true>(g_aggr2, wl, g_buf1, wr, bl, nullptr, g_buf2, M);
}

// ---------------- segment aggregation: out = sum(P)/max(sum(E),1e-16) ----------------
template <int C>
__device__ __forceinline__ void agg_body(const float* __restrict__ EP,
                                         float* __restrict__ out, int M)
{
    int w = (blockIdx.x * blockDim.x + threadIdx.x) >> 5;
    int lane = threadIdx.x & 31;
    if (w >= M) return;
    const int J = C / 32;
    float den[J], num[J];
#pragma unroll
    for (int j = 0; j < J; j++) { den[j] = 0.f; num[j] = 0.f; }
    int e0 = g_off[w], e1 = g_off[w + 1];
    for (int e = e0; e < e1; e++) {
        int s = g_srcs[e];
        const float2* row = (const float2*)(EP + (size_t)s * (2 * C));
#pragma unroll
        for (int j = 0; j < J; j++) {
            float2 v = __ldg(&row[lane + 32 * j]);
            den[j] += v.x;
            num[j] += v.y;
        }
    }
#pragma unroll
    for (int j = 0; j < J; j++)
        out[(size_t)w * C + lane + 32 * j] = num[j] / fmaxf(den[j], 1e-16f);
}

__global__ __launch_bounds__(256) void agg1_k(int M) { agg_body<64>(g_EP1, g_aggr1, M); }
__global__ __launch_bounds__(256) void agg2_k(int M) { agg_body<256>(g_EP2, g_aggr2, M); }

// ---------------- row L2-normalize + relu (in place) ----------------
template <int C>
__device__ __forceinline__ void norm_body(float* __restrict__ buf, int M)
{
    int w = (blockIdx.x * blockDim.x + threadIdx.x) >> 5;
    int lane = threadIdx.x & 31;
    if (w >= M) return;
    const int J = C / 32;
    float v[J];
    float ssq = 0.f;
    float* row = buf + (size_t)w * C;
#pragma unroll
    for (int j = 0; j < J; j++) {
        v[j] = row[lane + 32 * j];
        ssq += v[j] * v[j];
    }
#pragma unroll
    for (int o = 16; o > 0; o >>= 1) ssq += __shfl_xor_sync(0xffffffffu, ssq, o);
    float inv = 1.0f / fmaxf(sqrtf(ssq), 1e-12f);
#pragma unroll
    for (int j = 0; j < J; j++)
        row[lane + 32 * j] = fmaxf(v[j] * inv, 0.0f);
}

__global__ __launch_bounds__(256) void norm1_k(int M) { norm_body<256>(g_buf1, M); }
__global__ __launch_bounds__(256) void norm2_k(int M) { norm_body<128>(g_buf2, M); }

// ---------------- MemPooling assignment + S^T @ h2 accumulation ----------------
__global__ __launch_bounds__(256) void pool_k(const float* __restrict__ k_mem,
                                              const float* __restrict__ w_conv,
                                              int M)
{
    __shared__ float kk[16 * 128];
    __shared__ float k2s[16];
    __shared__ float wc[4];
    int t = threadIdx.x;
    for (int i = t; i < 16 * 128; i += 256) kk[i] = k_mem[i];
    __syncthreads();
    if (t < 16) {
        float s = 0.f;
        for (int f = 0; f < 128; f++) { float kv = kk[t * 128 + f]; s += kv * kv; }
        k2s[t] = s;
    }
    if (t < 4) wc[t] = w_conv[t];
    __syncthreads();

    int lane = t & 31;
    int gw = blockIdx.x * 8 + (t >> 5);
    int step = gridDim.x * 8;

    float acc[4][4];
#pragma unroll
    for (int k = 0; k < 4; k++)
#pragma unroll
        for (int j = 0; j < 4; j++) acc[k][j] = 0.f;

    for (int n = gw; n < M; n += step) {
        float x4[4];
        const float* row = g_buf2 + (size_t)n * 128;
        float xx = 0.f;
#pragma unroll
        for (int j = 0; j < 4; j++) {
            x4[j] = row[lane + 32 * j];
            xx += x4[j] * x4[j];
        }
#pragma unroll
        for (int o = 16; o > 0; o >>= 1) xx += __shfl_xor_sync(0xffffffffu, xx, o);

        float p[16];
#pragma unroll
        for (int i = 0; i < 16; i++) {
            float s = 0.f;
#pragma unroll
            for (int j = 0; j < 4; j++) s += kk[i * 128 + lane + 32 * j] * x4[j];
            p[i] = s;
        }
#pragma unroll
        for (int i = 0; i < 16; i++)
#pragma unroll
            for (int o = 16; o > 0; o >>= 1)
                p[i] += __shfl_xor_sync(0xffffffffu, p[i], o);

        float dist[16];
#pragma unroll
        for (int i = 0; i < 16; i++) {
            float d2 = fmaxf(k2s[i] + xx - 2.0f * p[i], 0.0f);
            dist[i] = 1.0f / (1.0f + d2);
        }
        float mix[4] = {0.f, 0.f, 0.f, 0.f};
#pragma unroll
        for (int h = 0; h < 4; h++) {
            float sh = dist[4 * h] + dist[4 * h + 1] + dist[4 * h + 2] + dist[4 * h + 3];
            float invh = wc[h] / sh;
#pragma unroll
            for (int k = 0; k < 4; k++) mix[k] += invh * dist[4 * h + k];
        }
        float mmax = fmaxf(fmaxf(mix[0], mix[1]), fmaxf(mix[2], mix[3]));
        float e[4], se = 0.f;
#pragma unroll
        for (int k = 0; k < 4; k++) { e[k] = __expf(mix[k] - mmax); se += e[k]; }
        float invse = 1.0f / se;
#pragma unroll
        for (int k = 0; k < 4; k++) {
            float s = e[k] * invse;
#pragma unroll
            for (int j = 0; j < 4; j++) acc[k][j] += s * x4[j];
        }
    }
#pragma unroll
    for (int k = 0; k < 4; k++)
#pragma unroll
        for (int j = 0; j < 4; j++)
            atomicAdd(&g_pool[k * 128 + lane + 32 * j], acc[k][j]);
}

// ---------------- head: memlin + mean pool + fx + LayerNorm + relu ----------------
__global__ __launch_bounds__(128) void final_k(const float* __restrict__ w_memlin,
                                               const float* __restrict__ b_memlin,
                                               const float* __restrict__ w_fx,
                                               const float* __restrict__ b_fx,
                                               const float* __restrict__ gamma,
                                               const float* __restrict__ beta,
                                               float* __restrict__ out)
{
    __shared__ float s_xp[512];
    __shared__ float s_g[128];
    __shared__ float s_y[64];
    __shared__ float s_mu, s_var;
    int t = threadIdx.x;
    for (int i = t; i < 512; i += 128) s_xp[i] = g_pool[i];
    __syncthreads();
    // g[c] = mean_k (xp[k]@w_memlin)[c] + b_memlin[c]
    {
        float s = 0.f;
        for (int k = 0; k < 4; k++) {
            float pk = 0.f;
            for (int f = 0; f < 128; f++) pk += s_xp[k * 128 + f] * w_memlin[f * 128 + t];
            s += pk;
        }
        s_g[t] = 0.25f * s + b_memlin[t];
    }
    __syncthreads();
    if (t < 64) {
        float y = b_fx[t];
        for (int c = 0; c < 128; c++) y += s_g[c] * w_fx[c * 64 + t];
        s_y[t] = y;
    }
    __syncthreads();
    if (t == 0) {
        float mu = 0.f;
        for (int i = 0; i < 64; i++) mu += s_y[i];
        mu *= (1.0f / 64.0f);
        float var = 0.f;
        for (int i = 0; i < 64; i++) { float d = s_y[i] - mu; var += d * d; }
        var *= (1.0f / 64.0f);
        s_mu = mu;
        s_var = var;
    }
    __syncthreads();
    if (t < 64) {
        float yv = (s_y[t] - s_mu) * rsqrtf(s_var + 1e-5f) * gamma[t] + beta[t];
        out[t] = fmaxf(yv, 0.0f);
    }
}

// ---------------- launch ----------------
extern "C" void kernel_launch(void* const* d_in, const int* in_sizes, int n_in,
                              void* d_out, int out_size)
{
    const float* x        = (const float*)d_in[0];
    const int*   ei       = (const int*)d_in[1];
    const float* w_proj1  = (const float*)d_in[2];
    const float* b_proj1  = (const float*)d_in[3];
    const float* t1       = (const float*)d_in[4];
    const float* w_l1     = (const float*)d_in[5];
    const float* b_l1     = (const float*)d_in[6];
    const float* w_r1     = (const float*)d_in[7];
    const float* w_proj2  = (const float*)d_in[8];
    const float* b_proj2  = (const float*)d_in[9];
    const float* t2       = (const float*)d_in[10];
    const float* w_l2     = (const float*)d_in[11];
    const float* b_l2     = (const float*)d_in[12];
    const float* w_r2     = (const float*)d_in[13];
    const float* k_mem    = (const float*)d_in[14];
    const float* w_conv   = (const float*)d_in[15];
    const float* w_memlin = (const float*)d_in[16];
    const float* b_memlin = (const float*)d_in[17];
    const float* w_fx     = (const float*)d_in[18];
    const float* b_fx     = (const float*)d_in[19];
    const float* gamma    = (const float*)d_in[20];
    const float* beta     = (const float*)d_in[21];
    float* out = (float*)d_out;

    int M = in_sizes[0] / 64;   // 50000
    int E = in_sizes[1] / 2;    // 800000

    int mb = (M + 63) / 64;     // 782
    int wb = (M + 7) / 8;       // warp-per-row blocks (256 thr = 8 warps)

    // CSR build + zero pool accumulator
    zero_k<<<(M + 255) / 256, 256>>>(M);
    count_k<<<(E + 255) / 256, 256>>>(ei, E);
    scan_k<<<1, 1024>>>(M);
    scatter_k<<<(E + 255) / 256, 256>>>(ei, E);

    // Layer 1
    gemm_ep1_k<<<dim3(1, mb), 256>>>(x, w_proj1, b_proj1, t1, M);
    agg1_k<<<wb, 256>>>(M);
    gemm_l1_k<<<dim3(4, mb), 256>>>(x, w_l1, b_l1, w_r1, M);
    norm1_k<<<wb, 256>>>(M);

    // Layer 2
    gemm_ep2_k<<<dim3(4, mb), 256>>>(w_proj2, b_proj2, t2, M);
    agg2_k<<<wb, 256>>>(M);
    gemm_l2_k<<<dim3(2, mb), 256>>>(w_l2, b_l2, w_r2, M);
    norm2_k<<<wb, 256>>>(M);

    // MemPooling + head
    pool_k<<<512, 256>>>(k_mem, w_conv, M);
    final_k<<<1, 128>>>(w_memlin, b_memlin, w_fx, b_fx, gamma, beta, out);
}

// round 5
// speedup vs baseline: 1.2128x; 1.2128x over previous
#include <cuda_runtime.h>
#include <cstdint>
#include <cstddef>

#define NN 50000
#define NE 800000

// ---------------- static scratch (no allocs allowed) ----------------
__device__ float g_EP1[(size_t)NN * 128];    // [n][2c] = (E,P) c<64
__device__ float g_aggr1[(size_t)NN * 64];
__device__ float g_buf1[(size_t)NN * 256];   // h1 (normalized+relu, fused epilogue)
__device__ float g_EP2[(size_t)NN * 512];    // [n][2c] c<256
__device__ float g_aggr2[(size_t)NN * 256];
__device__ float g_buf2[(size_t)NN * 128];   // h2
__device__ int   g_counts[NN];
__device__ int   g_off[NN + 1];
__device__ int   g_cur[NN];
__device__ int   g_srcs[NE];
__device__ int   g_bsum[64];
__device__ int   g_boff[64];
__device__ float g_pool[4 * 128];

// ---------------- f32x2 helpers (Blackwell packed fp32) ----------------
__device__ __forceinline__ unsigned long long dup2(float a) {
    unsigned long long r; unsigned int u = __float_as_uint(a);
    asm("mov.b64 %0, {%1, %1};" : "=l"(r) : "r"(u));
    return r;
}
__device__ __forceinline__ unsigned long long fma2(unsigned long long a,
                                                   unsigned long long b,
                                                   unsigned long long c) {
    unsigned long long d;
    asm("fma.rn.f32x2 %0, %1, %2, %3;" : "=l"(d) : "l"(a), "l"(b), "l"(c));
    return d;
}
__device__ __forceinline__ float2 unpk2(unsigned long long v) {
    unsigned int lo, hi;
    asm("mov.b64 {%0, %1}, %2;" : "=r"(lo), "=r"(hi) : "l"(v));
    return make_float2(__uint_as_float(lo), __uint_as_float(hi));
}

// ---------------- CSR build ----------------
__global__ void zero_k(int n) {
    int i = blockIdx.x * 256 + threadIdx.x;
    if (i < n) g_counts[i] = 0;
    if (i < 512) g_pool[i] = 0.0f;
}

__global__ void count_k(const int* __restrict__ ei, int E) {
    int i = blockIdx.x * 256 + threadIdx.x;
    if (i >= E) return;
    atomicAdd(&g_counts[ei[E + i]], 1);
}

// per-block inclusive scan of 1024-element chunks; partial sums to g_bsum
__global__ void scan1_k(int n) {
    __shared__ int s[1024];
    int t = threadIdx.x;
    int i = blockIdx.x * 1024 + t;
    int v = (i < n) ? g_counts[i] : 0;
    s[t] = v;
    __syncthreads();
    for (int o = 1; o < 1024; o <<= 1) {
        int a = (t >= o) ? s[t - o] : 0;
        __syncthreads();
        s[t] += a;
        __syncthreads();
    }
    if (i < n) g_off[i + 1] = s[t];   // partial (chunk-local) inclusive
    if (t == 1023) g_bsum[blockIdx.x] = s[1023];
}

__global__ void scan2_k(int nb) {
    if (threadIdx.x == 0) {
        int run = 0;
        for (int b = 0; b < nb; b++) { g_boff[b] = run; run += g_bsum[b]; }
    }
}

__global__ void scan3_k(int n) {
    int i = blockIdx.x * 256 + threadIdx.x;
    if (i >= n) return;
    int incl = g_off[i + 1] + g_boff[i >> 10];
    g_off[i + 1] = incl;
    if (i + 1 < n) g_cur[i + 1] = incl;
    if (i == 0) { g_off[0] = 0; g_cur[0] = 0; }
}

__global__ void scatter_k(const int* __restrict__ ei, int E) {
    int i = blockIdx.x * 256 + threadIdx.x;
    if (i >= E) return;
    int s = ei[i], d = ei[E + i];
    int pos = atomicAdd(&g_cur[d], 1);
    g_srcs[pos] = s;
}

// ---------------- full-N SIMT GEMM body, f32x2 inner loop ----------------
// C[M,N] = A[M,K1]@W[K1,N] (+ A2[M,K2]@W2[K2,N]) + bias
// One block covers BM=64 rows x ALL N columns (N in {64,128,256}).
// 256 threads; thread tile = 4 rows x (N/16) cols.
// EPI=0: +bias (and if NORM: row-L2-normalize + relu, fused).
// EPI=1: v=relu(acc+bias); write EP pairs (e, e*v), e=exp(v*t).
template <int EPI, int K1, int K2, int N, bool HAS2, bool NORM>
__device__ __forceinline__ void gemm_body(
    const float* __restrict__ A, const float* __restrict__ W,
    const float* __restrict__ A2, const float* __restrict__ W2,
    const float* __restrict__ bias, const float* __restrict__ tv,
    float* __restrict__ out, int M)
{
    constexpr int CPT = N / 64;          // 64-col chunks per thread
    __shared__ float As[16][64];
    __shared__ float Bs[16][N];
    int t = threadIdx.x;
    int m0 = blockIdx.y * 64;
    int lm = t >> 2, lk4 = (t & 3) * 4;  // A-tile load map
    int bk = t >> 4, bn4 = (t & 15) * 4; // B-tile load map
    int tx = t & 15, ty = t >> 4;

    unsigned long long acc[4][CPT][2];
#pragma unroll
    for (int i = 0; i < 4; i++)
#pragma unroll
        for (int c = 0; c < CPT; c++) { acc[i][c][0] = 0ull; acc[i][c][1] = 0ull; }

#pragma unroll 1
    for (int phase = 0; phase < (HAS2 ? 2 : 1); ++phase) {
        const float* Ap = phase ? A2 : A;
        const float* Wp = phase ? W2 : W;
        const int Kp = phase ? K2 : K1;
        const int nt = Kp / 16;
#pragma unroll 1
        for (int kt = 0; kt < nt; ++kt) {
            int kb = kt * 16;
            float4 av4 = make_float4(0.f, 0.f, 0.f, 0.f);
            int arow = m0 + lm;
            if (arow < M) av4 = *(const float4*)(Ap + (size_t)arow * Kp + kb + lk4);
            float4 bv4[CPT];
#pragma unroll
            for (int c = 0; c < CPT; c++)
                bv4[c] = *(const float4*)(Wp + (size_t)(kb + bk) * N + bn4 + 64 * c);
            __syncthreads();  // previous compute done before smem overwrite
            As[lk4 + 0][lm] = av4.x;
            As[lk4 + 1][lm] = av4.y;
            As[lk4 + 2][lm] = av4.z;
            As[lk4 + 3][lm] = av4.w;
#pragma unroll
            for (int c = 0; c < CPT; c++)
                *(float4*)&Bs[bk][bn4 + 64 * c] = bv4[c];
            __syncthreads();
#pragma unroll
            for (int k = 0; k < 16; k++) {
                float4 a = *(const float4*)&As[k][ty * 4];
                unsigned long long a0 = dup2(a.x), a1 = dup2(a.y),
                                   a2 = dup2(a.z), a3 = dup2(a.w);
#pragma unroll
                for (int c = 0; c < CPT; c++) {
                    ulonglong2 b = *(const ulonglong2*)&Bs[k][tx * 4 + 64 * c];
                    acc[0][c][0] = fma2(a0, b.x, acc[0][c][0]);
                    acc[0][c][1] = fma2(a0, b.y, acc[0][c][1]);
                    acc[1][c][0] = fma2(a1, b.x, acc[1][c][0]);
                    acc[1][c][1] = fma2(a1, b.y, acc[1][c][1]);
                    acc[2][c][0] = fma2(a2, b.x, acc[2][c][0]);
                    acc[2][c][1] = fma2(a2, b.y, acc[2][c][1]);
                    acc[3][c][0] = fma2(a3, b.x, acc[3][c][0]);
                    acc[3][c][1] = fma2(a3, b.y, acc[3][c][1]);
                }
            }
        }
    }

    // hoist per-column params (same cols for all 4 rows of this thread)
    float bias_r[CPT * 4];
    float tv_r[EPI ? CPT * 4 : 1];
#pragma unroll
    for (int c = 0; c < CPT; c++)
#pragma unroll
        for (int j = 0; j < 4; j++) {
            int col = tx * 4 + 64 * c + j;
            bias_r[c * 4 + j] = bias[col];
            if (EPI) tv_r[c * 4 + j] = tv[col];
        }

#pragma unroll
    for (int i = 0; i < 4; i++) {
        int row = m0 + ty * 4 + i;
        float v[CPT * 4];
#pragma unroll
        for (int c = 0; c < CPT; c++) {
            float2 c0 = unpk2(acc[i][c][0]);
            float2 c1 = unpk2(acc[i][c][1]);
            v[c * 4 + 0] = c0.x + bias_r[c * 4 + 0];
            v[c * 4 + 1] = c0.y + bias_r[c * 4 + 1];
            v[c * 4 + 2] = c1.x + bias_r[c * 4 + 2];
            v[c * 4 + 3] = c1.y + bias_r[c * 4 + 3];
        }
        if (EPI == 0) {
            float inv = 1.0f;
            if (NORM) {
                float ssq = 0.f;
#pragma unroll
                for (int j = 0; j < CPT * 4; j++) ssq += v[j] * v[j];
                // reduce across the 16 column-owning lanes (tx); lanes are
                // consecutive within the warp, xor masks stay inside 16.
#pragma unroll
                for (int o = 8; o > 0; o >>= 1)
                    ssq += __shfl_xor_sync(0xffffffffu, ssq, o);
                inv = 1.0f / fmaxf(sqrtf(ssq), 1e-12f);
            }
            if (row < M) {
#pragma unroll
                for (int c = 0; c < CPT; c++) {
                    float4 o;
                    if (NORM) {
                        o.x = fmaxf(v[c * 4 + 0] * inv, 0.0f);
                        o.y = fmaxf(v[c * 4 + 1] * inv, 0.0f);
                        o.z = fmaxf(v[c * 4 + 2] * inv, 0.0f);
                        o.w = fmaxf(v[c * 4 + 3] * inv, 0.0f);
                    } else {
                        o = make_float4(v[c * 4 + 0], v[c * 4 + 1],
                                        v[c * 4 + 2], v[c * 4 + 3]);
                    }
                    *(float4*)(out + (size_t)row * N + tx * 4 + 64 * c) = o;
                }
            }
        } else {
            if (row < M) {
#pragma unroll
                for (int c = 0; c < CPT; c++) {
                    float e[4], p[4];
#pragma unroll
                    for (int j = 0; j < 4; j++) {
                        float vv = fmaxf(v[c * 4 + j], 0.0f);
                        e[j] = __expf(vv * tv_r[c * 4 + j]);
                        p[j] = e[j] * vv;
                    }
                    float* base = out + (size_t)row * (2 * N) + 2 * (tx * 4 + 64 * c);
                    *(float4*)(base)     = make_float4(e[0], p[0], e[1], p[1]);
                    *(float4*)(base + 4) = make_float4(e[2], p[2], e[3], p[3]);
                }
            }
        }
    }
}

// ---- GEMM wrapper kernels ----
__global__ __launch_bounds__(256) void gemm_ep1_k(
    const float* __restrict__ x, const float* __restrict__ w,
    const float* __restrict__ b, const float* __restrict__ tv, int M)
{
    gemm_body<1, 64, 0, 64, false, false>(x, w, nullptr, nullptr, b, tv, g_EP1, M);
}
__global__ __launch_bounds__(256) void gemm_l1_k(
    const float* __restrict__ x, const float* __restrict__ wl,
    const float* __restrict__ bl, const float* __restrict__ wr, int M)
{
    gemm_body<0, 64, 64, 256, true, true>(g_aggr1, wl, x, wr, bl, nullptr, g_buf1, M);
}
__global__ __launch_bounds__(256) void gemm_ep2_k(
    const float* __restrict__ w, const float* __restrict__ b,
    const float* __restrict__ tv, int M)
{
    gemm_body<1, 256, 0, 256, false, false>(g_buf1, w, nullptr, nullptr, b, tv, g_EP2, M);
}
__global__ __launch_bounds__(256) void gemm_l2_k(
    const float* __restrict__ wl, const float* __restrict__ bl,
    const float* __restrict__ wr, int M)
{
    gemm_body<0, 256, 256, 128, true, true>(g_aggr2, wl, g_buf1, wr, bl, nullptr, g_buf2, M);
}

// ---------------- segment aggregation: out = sum(P)/max(sum(E),1e-16) ----------------
// float4 loads (two (E,P) channel pairs per load), 2-edge unroll for MLP.
template <int C>
__device__ __forceinline__ void agg_body(const float* __restrict__ EP,
                                         float* __restrict__ out, int M)
{
    int w = (blockIdx.x * blockDim.x + threadIdx.x) >> 5;
    int lane = threadIdx.x & 31;
    if (w >= M) return;
    constexpr int J = C / 64;   // float4s per lane per row
    float den[2 * J], num[2 * J];
#pragma unroll
    for (int j = 0; j < 2 * J; j++) { den[j] = 0.f; num[j] = 0.f; }
    int e0 = g_off[w], e1 = g_off[w + 1];
    int e = e0;
    for (; e + 1 < e1; e += 2) {
        int s0 = g_srcs[e], s1 = g_srcs[e + 1];
        const float4* r0 = (const float4*)(EP + (size_t)s0 * (2 * C));
        const float4* r1 = (const float4*)(EP + (size_t)s1 * (2 * C));
        float4 a[J], b[J];
#pragma unroll
        for (int j = 0; j < J; j++) a[j] = __ldg(&r0[lane + 32 * j]);
#pragma unroll
        for (int j = 0; j < J; j++) b[j] = __ldg(&r1[lane + 32 * j]);
#pragma unroll
        for (int j = 0; j < J; j++) {
            den[2 * j]     += a[j].x + b[j].x;
            num[2 * j]     += a[j].y + b[j].y;
            den[2 * j + 1] += a[j].z + b[j].z;
            num[2 * j + 1] += a[j].w + b[j].w;
        }
    }
    if (e < e1) {
        int s0 = g_srcs[e];
        const float4* r0 = (const float4*)(EP + (size_t)s0 * (2 * C));
#pragma unroll
        for (int j = 0; j < J; j++) {
            float4 a = __ldg(&r0[lane + 32 * j]);
            den[2 * j]     += a.x;
            num[2 * j]     += a.y;
            den[2 * j + 1] += a.z;
            num[2 * j + 1] += a.w;
        }
    }
#pragma unroll
    for (int j = 0; j < J; j++) {
        float2 o;
        o.x = num[2 * j]     / fmaxf(den[2 * j],     1e-16f);
        o.y = num[2 * j + 1] / fmaxf(den[2 * j + 1], 1e-16f);
        *(float2*)(out + (size_t)w * C + 2 * lane + 64 * j) = o;
    }
}

__global__ __launch_bounds__(256) void agg1_k(int M) { agg_body<64>(g_EP1, g_aggr1, M); }
__global__ __launch_bounds__(256) void agg2_k(int M) { agg_body<256>(g_EP2, g_aggr2, M); }

// ---------------- MemPooling assignment + S^T @ h2 accumulation ----------------
__global__ __launch_bounds__(256) void pool_k(const float* __restrict__ k_mem,
                                              const float* __restrict__ w_conv,
                                              int M)
{
    __shared__ float kk[16 * 128];
    __shared__ float k2s[16];
    __shared__ float wc[4];
    int t = threadIdx.x;
    for (int i = t; i < 16 * 128; i += 256) kk[i] = k_mem[i];
    __syncthreads();
    if (t < 16) {
        float s = 0.f;
        for (int f = 0; f < 128; f++) { float kv = kk[t * 128 + f]; s += kv * kv; }
        k2s[t] = s;
    }
    if (t < 4) wc[t] = w_conv[t];
    __syncthreads();

    int lane = t & 31;
    int gw = blockIdx.x * 8 + (t >> 5);
    int step = gridDim.x * 8;

    float acc[4][4];
#pragma unroll
    for (int k = 0; k < 4; k++)
#pragma unroll
        for (int j = 0; j < 4; j++) acc[k][j] = 0.f;

    for (int n = gw; n < M; n += step) {
        float x4[4];
        const float* row = g_buf2 + (size_t)n * 128;
        float xx = 0.f;
#pragma unroll
        for (int j = 0; j < 4; j++) {
            x4[j] = row[lane + 32 * j];
            xx += x4[j] * x4[j];
        }
#pragma unroll
        for (int o = 16; o > 0; o >>= 1) xx += __shfl_xor_sync(0xffffffffu, xx, o);

        float p[16];
#pragma unroll
        for (int i = 0; i < 16; i++) {
            float s = 0.f;
#pragma unroll
            for (int j = 0; j < 4; j++) s += kk[i * 128 + lane + 32 * j] * x4[j];
            p[i] = s;
        }
#pragma unroll
        for (int i = 0; i < 16; i++)
#pragma unroll
            for (int o = 16; o > 0; o >>= 1)
                p[i] += __shfl_xor_sync(0xffffffffu, p[i], o);

        float dist[16];
#pragma unroll
        for (int i = 0; i < 16; i++) {
            float d2 = fmaxf(k2s[i] + xx - 2.0f * p[i], 0.0f);
            dist[i] = 1.0f / (1.0f + d2);
        }
        float mix[4] = {0.f, 0.f, 0.f, 0.f};
#pragma unroll
        for (int h = 0; h < 4; h++) {
            float sh = dist[4 * h] + dist[4 * h + 1] + dist[4 * h + 2] + dist[4 * h + 3];
            float invh = wc[h] / sh;
#pragma unroll
            for (int k = 0; k < 4; k++) mix[k] += invh * dist[4 * h + k];
        }
        float mmax = fmaxf(fmaxf(mix[0], mix[1]), fmaxf(mix[2], mix[3]));
        float e[4], se = 0.f;
#pragma unroll
        for (int k = 0; k < 4; k++) { e[k] = __expf(mix[k] - mmax); se += e[k]; }
        float invse = 1.0f / se;
#pragma unroll
        for (int k = 0; k < 4; k++) {
            float s = e[k] * invse;
#pragma unroll
            for (int j = 0; j < 4; j++) acc[k][j] += s * x4[j];
        }
    }
#pragma unroll
    for (int k = 0; k < 4; k++)
#pragma unroll
        for (int j = 0; j < 4; j++)
            atomicAdd(&g_pool[k * 128 + lane + 32 * j], acc[k][j]);
}

// ---------------- head: memlin + mean pool + fx + LayerNorm + relu ----------------
__global__ __launch_bounds__(128) void final_k(const float* __restrict__ w_memlin,
                                               const float* __restrict__ b_memlin,
                                               const float* __restrict__ w_fx,
                                               const float* __restrict__ b_fx,
                                               const float* __restrict__ gamma,
                                               const float* __restrict__ beta,
                                               float* __restrict__ out)
{
    __shared__ float s_xp[512];
    __shared__ float s_g[128];
    __shared__ float s_y[64];
    __shared__ float s_mu, s_var;
    int t = threadIdx.x;
    for (int i = t; i < 512; i += 128) s_xp[i] = g_pool[i];
    __syncthreads();
    {
        float s = 0.f;
        for (int k = 0; k < 4; k++) {
            float pk = 0.f;
            for (int f = 0; f < 128; f++) pk += s_xp[k * 128 + f] * w_memlin[f * 128 + t];
            s += pk;
        }
        s_g[t] = 0.25f * s + b_memlin[t];
    }
    __syncthreads();
    if (t < 64) {
        float y = b_fx[t];
        for (int c = 0; c < 128; c++) y += s_g[c] * w_fx[c * 64 + t];
        s_y[t] = y;
    }
    __syncthreads();
    if (t == 0) {
        float mu = 0.f;
        for (int i = 0; i < 64; i++) mu += s_y[i];
        mu *= (1.0f / 64.0f);
        float var = 0.f;
        for (int i = 0; i < 64; i++) { float d = s_y[i] - mu; var += d * d; }
        var *= (1.0f / 64.0f);
        s_mu = mu;
        s_var = var;
    }
    __syncthreads();
    if (t < 64) {
        float yv = (s_y[t] - s_mu) * rsqrtf(s_var + 1e-5f) * gamma[t] + beta[t];
        out[t] = fmaxf(yv, 0.0f);
    }
}

// ---------------- launch ----------------
extern "C" void kernel_launch(void* const* d_in, const int* in_sizes, int n_in,
                              void* d_out, int out_size)
{
    const float* x        = (const float*)d_in[0];
    const int*   ei       = (const int*)d_in[1];
    const float* w_proj1  = (const float*)d_in[2];
    const float* b_proj1  = (const float*)d_in[3];
    const float* t1       = (const float*)d_in[4];
    const float* w_l1     = (const float*)d_in[5];
    const float* b_l1     = (const float*)d_in[6];
    const float* w_r1     = (const float*)d_in[7];
    const float* w_proj2  = (const float*)d_in[8];
    const float* b_proj2  = (const float*)d_in[9];
    const float* t2       = (const float*)d_in[10];
    const float* w_l2     = (const float*)d_in[11];
    const float* b_l2     = (const float*)d_in[12];
    const float* w_r2     = (const float*)d_in[13];
    const float* k_mem    = (const float*)d_in[14];
    const float* w_conv   = (const float*)d_in[15];
    const float* w_memlin = (const float*)d_in[16];
    const float* b_memlin = (const float*)d_in[17];
    const float* w_fx     = (const float*)d_in[18];
    const float* b_fx     = (const float*)d_in[19];
    const float* gamma    = (const float*)d_in[20];
    const float* beta     = (const float*)d_in[21];
    float* out = (float*)d_out;

    int M = in_sizes[0] / 64;   // 50000
    int E = in_sizes[1] / 2;    // 800000

    int mb = (M + 63) / 64;     // row-tile blocks (782)
    int wb = (M + 7) / 8;       // warp-per-row blocks (256 thr = 8 warps)
    int nb = (M + 1023) / 1024; // scan chunks (49)

    // CSR build + zero pool accumulator
    zero_k<<<(M + 255) / 256, 256>>>(M);
    count_k<<<(E + 255) / 256, 256>>>(ei, E);
    scan1_k<<<nb, 1024>>>(M);
    scan2_k<<<1, 32>>>(nb);
    scan3_k<<<(M + 255) / 256, 256>>>(M);
    scatter_k<<<(E + 255) / 256, 256>>>(ei, E);

    // Layer 1
    gemm_ep1_k<<<dim3(1, mb), 256>>>(x, w_proj1, b_proj1, t1, M);
    agg1_k<<<wb, 256>>>(M);
    gemm_l1_k<<<dim3(1, mb), 256>>>(x, w_l1, b_l1, w_r1, M);   // fused norm+relu

    // Layer 2
    gemm_ep2_k<<<dim3(1, mb), 256>>>(w_proj2, b_proj2, t2, M);
    agg2_k<<<wb, 256>>>(M);
    gemm_l2_k<<<dim3(1, mb), 256>>>(w_l2, b_l2, w_r2, M);      // fused norm+relu

    // MemPooling + head
    pool_k<<<512, 256>>>(k_mem, w_conv, M);
    final_k<<<1, 128>>>(w_memlin, b_memlin, w_fx, b_fx, gamma, beta, out);
}

// round 7
// speedup vs baseline: 1.3750x; 1.1337x over previous
#include <cuda_runtime.h>
#include <cuda_fp16.h>
#include <cstdint>
#include <cstddef>

#define NN 50000
#define NE 800000

// ---------------- static scratch (no allocs allowed) ----------------
__device__ __half2 g_EP1[(size_t)NN * 64];    // [n][c] = (E,P) half2, c<64
__device__ float   g_aggr1[(size_t)NN * 64];
__device__ float   g_buf1[(size_t)NN * 256];  // h1 (normalized+relu, fused epilogue)
__device__ __half2 g_EP2[(size_t)NN * 256];   // [n][c] c<256
__device__ float   g_aggr2[(size_t)NN * 256];
__device__ float   g_buf2[(size_t)NN * 128];  // h2
__device__ int     g_counts[NN];
__device__ int     g_off[NN + 1];
__device__ int     g_cur[NN];
__device__ int     g_srcs[NE];
__device__ int     g_bsum[64];
__device__ int     g_boff[64];
__device__ float   g_pool[4 * 128];

// ---------------- f32x2 helpers (Blackwell packed fp32) ----------------
__device__ __forceinline__ unsigned long long dup2(float a) {
    unsigned long long r; unsigned int u = __float_as_uint(a);
    asm("mov.b64 %0, {%1, %1};" : "=l"(r) : "r"(u));
    return r;
}
__device__ __forceinline__ unsigned long long fma2(unsigned long long a,
                                                   unsigned long long b,
                                                   unsigned long long c) {
    unsigned long long d;
    asm("fma.rn.f32x2 %0, %1, %2, %3;" : "=l"(d) : "l"(a), "l"(b), "l"(c));
    return d;
}
__device__ __forceinline__ float2 unpk2(unsigned long long v) {
    unsigned int lo, hi;
    asm("mov.b64 {%0, %1}, %2;" : "=r"(lo), "=r"(hi) : "l"(v));
    return make_float2(__uint_as_float(lo), __uint_as_float(hi));
}

// ---------------- CSR build ----------------
__global__ void zero_k(int n) {
    int i = blockIdx.x * 256 + threadIdx.x;
    if (i < n) g_counts[i] = 0;
    if (i < 512) g_pool[i] = 0.0f;
}

__global__ void count_k(const int* __restrict__ ei, int E) {
    int i = blockIdx.x * 256 + threadIdx.x;
    if (i >= E) return;
    atomicAdd(&g_counts[ei[E + i]], 1);
}

// per-block inclusive scan of 1024-element chunks; partial sums to g_bsum
__global__ void scan1_k(int n) {
    __shared__ int s[1024];
    int t = threadIdx.x;
    int i = blockIdx.x * 1024 + t;
    int v = (i < n) ? g_counts[i] : 0;
    s[t] = v;
    __syncthreads();
    for (int o = 1; o < 1024; o <<= 1) {
        int a = (t >= o) ? s[t - o] : 0;
        __syncthreads();
        s[t] += a;
        __syncthreads();
    }
    if (i < n) g_off[i + 1] = s[t];   // partial (chunk-local) inclusive
    if (t == 1023) g_bsum[blockIdx.x] = s[1023];
}

// parallel exclusive scan of the (<=64) block sums
__global__ void scan2_k(int nb) {
    __shared__ int s[64];
    int t = threadIdx.x;  // 64 threads
    int v = (t < nb) ? g_bsum[t] : 0;
    s[t] = v;
    __syncthreads();
    for (int o = 1; o < 64; o <<= 1) {
        int a = (t >= o) ? s[t - o] : 0;
        __syncthreads();
        s[t] += a;
        __syncthreads();
    }
    if (t < nb) g_boff[t] = s[t] - v;  // exclusive
}

__global__ void scan3_k(int n) {
    int i = blockIdx.x * 256 + threadIdx.x;
    if (i >= n) return;
    int incl = g_off[i + 1] + g_boff[i >> 10];
    g_off[i + 1] = incl;
    if (i + 1 < n) g_cur[i + 1] = incl;
    if (i == 0) { g_off[0] = 0; g_cur[0] = 0; }
}

__global__ void scatter_k(const int* __restrict__ ei, int E) {
    int i = blockIdx.x * 256 + threadIdx.x;
    if (i >= E) return;
    int s = ei[i], d = ei[E + i];
    int pos = atomicAdd(&g_cur[d], 1);
    g_srcs[pos] = s;
}

// ---------------- full-N SIMT GEMM body, f32x2 inner loop ----------------
// C[M,N] = A[M,K1]@W[K1,N] (+ A2[M,K2]@W2[K2,N]) + bias
// One block covers BM=64 rows x ALL N columns (N in {64,128,256}).
// 256 threads; thread tile = 4 rows x (N/16) cols.
// EPI=0: +bias (and if NORM: row-L2-normalize + relu, fused).
// EPI=1: v=relu(acc+bias); write fp16 EP pairs half2(e, e*v), e=exp(v*t).
template <int EPI, int K1, int K2, int N, bool HAS2, bool NORM>
__device__ __forceinline__ void gemm_body(
    const float* __restrict__ A, const float* __restrict__ W,
    const float* __restrict__ A2, const float* __restrict__ W2,
    const float* __restrict__ bias, const float* __restrict__ tv,
    float* __restrict__ outf, __half2* __restrict__ outh, int M)
{
    constexpr int CPT = N / 64;          // 64-col chunks per thread
    __shared__ float As[16][64];
    __shared__ float Bs[16][N];
    int t = threadIdx.x;
    int m0 = blockIdx.y * 64;
    int lm = t >> 2, lk4 = (t & 3) * 4;  // A-tile load map
    int bk = t >> 4, bn4 = (t & 15) * 4; // B-tile load map
    int tx = t & 15, ty = t >> 4;

    unsigned long long acc[4][CPT][2];
#pragma unroll
    for (int i = 0; i < 4; i++)
#pragma unroll
        for (int c = 0; c < CPT; c++) { acc[i][c][0] = 0ull; acc[i][c][1] = 0ull; }

#pragma unroll 1
    for (int phase = 0; phase < (HAS2 ? 2 : 1); ++phase) {
        const float* Ap = phase ? A2 : A;
        const float* Wp = phase ? W2 : W;
        const int Kp = phase ? K2 : K1;
        const int nt = Kp / 16;
#pragma unroll 1
        for (int kt = 0; kt < nt; ++kt) {
            int kb = kt * 16;
            float4 av4 = make_float4(0.f, 0.f, 0.f, 0.f);
            int arow = m0 + lm;
            if (arow < M) av4 = *(const float4*)(Ap + (size_t)arow * Kp + kb + lk4);
            float4 bv4[CPT];
#pragma unroll
            for (int c = 0; c < CPT; c++)
                bv4[c] = *(const float4*)(Wp + (size_t)(kb + bk) * N + bn4 + 64 * c);
            __syncthreads();  // previous compute done before smem overwrite
            As[lk4 + 0][lm] = av4.x;
            As[lk4 + 1][lm] = av4.y;
            As[lk4 + 2][lm] = av4.z;
            As[lk4 + 3][lm] = av4.w;
#pragma unroll
            for (int c = 0; c < CPT; c++)
                *(float4*)&Bs[bk][bn4 + 64 * c] = bv4[c];
            __syncthreads();
#pragma unroll
            for (int k = 0; k < 16; k++) {
                float4 a = *(const float4*)&As[k][ty * 4];
                unsigned long long a0 = dup2(a.x), a1 = dup2(a.y),
                                   a2 = dup2(a.z), a3 = dup2(a.w);
#pragma unroll
                for (int c = 0; c < CPT; c++) {
                    ulonglong2 b = *(const ulonglong2*)&Bs[k][tx * 4 + 64 * c];
                    acc[0][c][0] = fma2(a0, b.x, acc[0][c][0]);
                    acc[0][c][1] = fma2(a0, b.y, acc[0][c][1]);
                    acc[1][c][0] = fma2(a1, b.x, acc[1][c][0]);
                    acc[1][c][1] = fma2(a1, b.y, acc[1][c][1]);
                    acc[2][c][0] = fma2(a2, b.x, acc[2][c][0]);
                    acc[2][c][1] = fma2(a2, b.y, acc[2][c][1]);
                    acc[3][c][0] = fma2(a3, b.x, acc[3][c][0]);
                    acc[3][c][1] = fma2(a3, b.y, acc[3][c][1]);
                }
            }
        }
    }

    // hoist per-column params (same cols for all 4 rows of this thread)
    float bias_r[CPT * 4];
    float tv_r[EPI ? CPT * 4 : 1];
#pragma unroll
    for (int c = 0; c < CPT; c++)
#pragma unroll
        for (int j = 0; j < 4; j++) {
            int col = tx * 4 + 64 * c + j;
            bias_r[c * 4 + j] = bias[col];
            if (EPI) tv_r[c * 4 + j] = tv[col];
        }

#pragma unroll
    for (int i = 0; i < 4; i++) {
        int row = m0 + ty * 4 + i;
        float v[CPT * 4];
#pragma unroll
        for (int c = 0; c < CPT; c++) {
            float2 c0 = unpk2(acc[i][c][0]);
            float2 c1 = unpk2(acc[i][c][1]);
            v[c * 4 + 0] = c0.x + bias_r[c * 4 + 0];
            v[c * 4 + 1] = c0.y + bias_r[c * 4 + 1];
            v[c * 4 + 2] = c1.x + bias_r[c * 4 + 2];
            v[c * 4 + 3] = c1.y + bias_r[c * 4 + 3];
        }
        if (EPI == 0) {
            float inv = 1.0f;
            if (NORM) {
                float ssq = 0.f;
#pragma unroll
                for (int j = 0; j < CPT * 4; j++) ssq += v[j] * v[j];
                // reduce across the 16 column-owning lanes (tx)
#pragma unroll
                for (int o = 8; o > 0; o >>= 1)
                    ssq += __shfl_xor_sync(0xffffffffu, ssq, o);
                inv = 1.0f / fmaxf(sqrtf(ssq), 1e-12f);
            }
            if (row < M) {
#pragma unroll
                for (int c = 0; c < CPT; c++) {
                    float4 o;
                    if (NORM) {
                        o.x = fmaxf(v[c * 4 + 0] * inv, 0.0f);
                        o.y = fmaxf(v[c * 4 + 1] * inv, 0.0f);
                        o.z = fmaxf(v[c * 4 + 2] * inv, 0.0f);
                        o.w = fmaxf(v[c * 4 + 3] * inv, 0.0f);
                    } else {
                        o = make_float4(v[c * 4 + 0], v[c * 4 + 1],
                                        v[c * 4 + 2], v[c * 4 + 3]);
                    }
                    *(float4*)(outf + (size_t)row * N + tx * 4 + 64 * c) = o;
                }
            }
        } else {
            if (row < M) {
#pragma unroll
                for (int c = 0; c < CPT; c++) {
                    __half2 hp[4];
#pragma unroll
                    for (int j = 0; j < 4; j++) {
                        float vv = fmaxf(v[c * 4 + j], 0.0f);
                        float e = __expf(vv * tv_r[c * 4 + j]);
                        hp[j] = __floats2half2_rn(e, e * vv);   // (E, P)
                    }
                    // 4 consecutive channels = one uint4; row = N half2
                    uint4* rowp = (uint4*)(outh + (size_t)row * N);
                    rowp[tx + 16 * c] = *(const uint4*)hp;
                }
            }
        }
    }
}

// ---- GEMM wrapper kernels ----
__global__ __launch_bounds__(256) void gemm_ep1_k(
    const float* __restrict__ x, const float* __restrict__ w,
    const float* __restrict__ b, const float* __restrict__ tv, int M)
{
    gemm_body<1, 64, 0, 64, false, false>(x, w, nullptr, nullptr, b, tv,
                                          nullptr, g_EP1, M);
}
__global__ __launch_bounds__(256) void gemm_l1_k(
    const float* __restrict__ x, const float* __restrict__ wl,
    const float* __restrict__ bl, const float* __restrict__ wr, int M)
{
    gemm_body<0, 64, 64, 256, true, true>(g_aggr1, wl, x, wr, bl, nullptr,
                                          g_buf1, nullptr, M);
}
__global__ __launch_bounds__(256) void gemm_ep2_k(
    const float* __restrict__ w, const float* __restrict__ b,
    const float* __restrict__ tv, int M)
{
    gemm_body<1, 256, 0, 256, false, false>(g_buf1, w, nullptr, nullptr, b, tv,
                                            nullptr, g_EP2, M);
}
__global__ __launch_bounds__(256) void gemm_l2_k(
    const float* __restrict__ wl, const float* __restrict__ bl,
    const float* __restrict__ wr, int M)
{
    gemm_body<0, 256, 256, 128, true, true>(g_aggr2, wl, g_buf1, wr, bl, nullptr,
                                            g_buf2, nullptr, M)
;}

// ---------------- segment aggregation: out = sum(P)/max(sum(E),1e-16) ----------------
// fp16 (E,P) pairs, channel-major half2 layout; fp32 accumulation.
// C=256: per lane 2x uint4 (8 channels). C=64: per lane 1x uint2 (2 channels).
__device__ __forceinline__ void acc_u4(uint4 u, float* den, float* num) {
    const __half2* h = (const __half2*)&u;
#pragma unroll
    for (int k = 0; k < 4; k++) {
        float2 f = __half22float2(h[k]);
        den[k] += f.x;
        num[k] += f.y;
    }
}

__global__ __launch_bounds__(256) void agg2_k(int M)  // C=256
{
    int w = (blockIdx.x * blockDim.x + threadIdx.x) >> 5;
    int lane = threadIdx.x & 31;
    if (w >= M) return;
    float den[8], num[8];
#pragma unroll
    for (int j = 0; j < 8; j++) { den[j] = 0.f; num[j] = 0.f; }
    int e0 = g_off[w], e1 = g_off[w + 1];
    int e = e0;
    for (; e + 1 < e1; e += 2) {
        int s0 = g_srcs[e], s1 = g_srcs[e + 1];
        const uint4* r0 = (const uint4*)(g_EP2 + (size_t)s0 * 256);
        const uint4* r1 = (const uint4*)(g_EP2 + (size_t)s1 * 256);
        uint4 a0 = __ldg(&r0[lane]), a1 = __ldg(&r0[lane + 32]);
        uint4 b0 = __ldg(&r1[lane]), b1 = __ldg(&r1[lane + 32]);
        acc_u4(a0, den, num);
        acc_u4(a1, den + 4, num + 4);
        acc_u4(b0, den, num);
        acc_u4(b1, den + 4, num + 4);
    }
    if (e < e1) {
        const uint4* r0 = (const uint4*)(g_EP2 + (size_t)g_srcs[e] * 256);
        uint4 a0 = __ldg(&r0[lane]), a1 = __ldg(&r0[lane + 32]);
        acc_u4(a0, den, num);
        acc_u4(a1, den + 4, num + 4);
    }
#pragma unroll
    for (int h = 0; h < 2; h++) {
        float4 o;
        o.x = num[4 * h + 0] / fmaxf(den[4 * h + 0], 1e-16f);
        o.y = num[4 * h + 1] / fmaxf(den[4 * h + 1], 1e-16f);
        o.z = num[4 * h + 2] / fmaxf(den[4 * h + 2], 1e-16f);
        o.w = num[4 * h + 3] / fmaxf(den[4 * h + 3], 1e-16f);
        *(float4*)(g_aggr2 + (size_t)w * 256 + 4 * (lane + 32 * h)) = o;
    }
}

__global__ __launch_bounds__(256) void agg1_k(int M)  // C=64
{
    int w = (blockIdx.x * blockDim.x + threadIdx.x) >> 5;
    int lane = threadIdx.x & 31;
    if (w >= M) return;
    float den[2] = {0.f, 0.f}, num[2] = {0.f, 0.f};
    int e0 = g_off[w], e1 = g_off[w + 1];
    int e = e0;
    for (; e + 1 < e1; e += 2) {
        int s0 = g_srcs[e], s1 = g_srcs[e + 1];
        uint2 a = __ldg((const uint2*)(g_EP1 + (size_t)s0 * 64) + lane);
        uint2 b = __ldg((const uint2*)(g_EP1 + (size_t)s1 * 64) + lane);
        float2 f0 = __half22float2(*(const __half2*)&a.x);
        float2 f1 = __half22float2(*(const __half2*)&a.y);
        float2 f2 = __half22float2(*(const __half2*)&b.x);
        float2 f3 = __half22float2(*(const __half2*)&b.y);
        den[0] += f0.x + f2.x; num[0] += f0.y + f2.y;
        den[1] += f1.x + f3.x; num[1] += f1.y + f3.y;
    }
    if (e < e1) {
        uint2 a = __ldg((const uint2*)(g_EP1 + (size_t)g_srcs[e] * 64) + lane);
        float2 f0 = __half22float2(*(const __half2*)&a.x);
        float2 f1 = __half22float2(*(const __half2*)&a.y);
        den[0] += f0.x; num[0] += f0.y;
        den[1] += f1.x; num[1] += f1.y;
    }
    float2 o;
    o.x = num[0] / fmaxf(den[0], 1e-16f);
    o.y = num[1] / fmaxf(den[1], 1e-16f);
    *(float2*)(g_aggr1 + (size_t)w * 64 + 2 * lane) = o;
}

// ---------------- MemPooling assignment + S^T @ h2 accumulation ----------------
__global__ __launch_bounds__(256) void pool_k(const float* __restrict__ k_mem,
                                              const float* __restrict__ w_conv,
                                              int M)
{
    __shared__ float kk[16 * 128];
    __shared__ float k2s[16];
    __shared__ float wc[4];
    int t = threadIdx.x;
    for (int i = t; i < 16 * 128; i += 256) kk[i] = k_mem[i];
    __syncthreads();
    if (t < 16) {
        float s = 0.f;
        for (int f = 0; f < 128; f++) { float kv = kk[t * 128 + f]; s += kv * kv; }
        k2s[t] = s;
    }
    if (t < 4) wc[t] = w_conv[t];
    __syncthreads();

    int lane = t & 31;
    int gw = blockIdx.x * 8 + (t >> 5);
    int step = gridDim.x * 8;

    float acc[4][4];
#pragma unroll
    for (int k = 0; k < 4; k++)
#pragma unroll
        for (int j = 0; j < 4; j++) acc[k][j] = 0.f;

    for (int n = gw; n < M; n += step) {
        float x4[4];
        const float* row = g_buf2 + (size_t)n * 128;
        float xx = 0.f;
#pragma unroll
        for (int j = 0; j < 4; j++) {
            x4[j] = row[lane + 32 * j];
            xx += x4[j] * x4[j];
        }
#pragma unroll
        for (int o = 16; o > 0; o >>= 1) xx += __shfl_xor_sync(0xffffffffu, xx, o);

        float p[16];
#pragma unroll
        for (int i = 0; i < 16; i++) {
            float s = 0.f;
#pragma unroll
            for (int j = 0; j < 4; j++) s += kk[i * 128 + lane + 32 * j] * x4[j];
            p[i] = s;
        }
#pragma unroll
        for (int i = 0; i < 16; i++)
#pragma unroll
            for (int o = 16; o > 0; o >>= 1)
                p[i] += __shfl_xor_sync(0xffffffffu, p[i], o);

        float dist[16];
#pragma unroll
        for (int i = 0; i < 16; i++) {
            float d2 = fmaxf(k2s[i] + xx - 2.0f * p[i], 0.0f);
            dist[i] = 1.0f / (1.0f + d2);
        }
        float mix[4] = {0.f, 0.f, 0.f, 0.f};
#pragma unroll
        for (int h = 0; h < 4; h++) {
            float sh = dist[4 * h] + dist[4 * h + 1] + dist[4 * h + 2] + dist[4 * h + 3];
            float invh = wc[h] / sh;
#pragma unroll
            for (int k = 0; k < 4; k++) mix[k] += invh * dist[4 * h + k];
        }
        float mmax = fmaxf(fmaxf(mix[0], mix[1]), fmaxf(mix[2], mix[3]));
        float e[4], se = 0.f;
#pragma unroll
        for (int k = 0; k < 4; k++) { e[k] = __expf(mix[k] - mmax); se += e[k]; }
        float invse = 1.0f / se;
#pragma unroll
        for (int k = 0; k < 4; k++) {
            float s = e[k] * invse;
#pragma unroll
            for (int j = 0; j < 4; j++) acc[k][j] += s * x4[j];
        }
    }
#pragma unroll
    for (int k = 0; k < 4; k++)
#pragma unroll
        for (int j = 0; j < 4; j++)
            atomicAdd(&g_pool[k * 128 + lane + 32 * j], acc[k][j]);
}

// ---------------- head: memlin + mean pool + fx + LayerNorm + relu ----------------
__global__ __launch_bounds__(128) void final_k(const float* __restrict__ w_memlin,
                                               const float* __restrict__ b_memlin,
                                               const float* __restrict__ w_fx,
                                               const float* __restrict__ b_fx,
                                               const float* __restrict__ gamma,
                                               const float* __restrict__ beta,
                                               float* __restrict__ out)
{
    __shared__ float s_xp[512];
    __shared__ float s_g[128];
    __shared__ float s_y[64];
    __shared__ float s_mu, s_var;
    int t = threadIdx.x;
    for (int i = t; i < 512; i += 128) s_xp[i] = g_pool[i];
    __syncthreads();
    {
        float s = 0.f;
        for (int k = 0; k < 4; k++) {
            float pk = 0.f;
            for (int f = 0; f < 128; f++) pk += s_xp[k * 128 + f] * w_memlin[f * 128 + t];
            s += pk;
        }
        s_g[t] = 0.25f * s + b_memlin[t];
    }
    __syncthreads();
    if (t < 64) {
        float y = b_fx[t];
        for (int c = 0; c < 128; c++) y += s_g[c] * w_fx[c * 64 + t];
        s_y[t] = y;
    }
    __syncthreads();
    if (t == 0) {
        float mu = 0.f;
        for (int i = 0; i < 64; i++) mu += s_y[i];
        mu *= (1.0f / 64.0f);
        float var = 0.f;
        for (int i = 0; i < 64; i++) { float d = s_y[i] - mu; var += d * d; }
        var *= (1.0f / 64.0f);
        s_mu = mu;
        s_var = var;
    }
    __syncthreads();
    if (t < 64) {
        float yv = (s_y[t] - s_mu) * rsqrtf(s_var + 1e-5f) * gamma[t] + beta[t];
        out[t] = fmaxf(yv, 0.0f);
    }
}

// ---------------- launch ----------------
extern "C" void kernel_launch(void* const* d_in, const int* in_sizes, int n_in,
                              void* d_out, int out_size)
{
    const float* x        = (const float*)d_in[0];
    const int*   ei       = (const int*)d_in[1];
    const float* w_proj1  = (const float*)d_in[2];
    const float* b_proj1  = (const float*)d_in[3];
    const float* t1       = (const float*)d_in[4];
    const float* w_l1     = (const float*)d_in[5];
    const float* b_l1     = (const float*)d_in[6];
    const float* w_r1     = (const float*)d_in[7];
    const float* w_proj2  = (const float*)d_in[8];
    const float* b_proj2  = (const float*)d_in[9];
    const float* t2       = (const float*)d_in[10];
    const float* w_l2     = (const float*)d_in[11];
    const float* b_l2     = (const float*)d_in[12];
    const float* w_r2     = (const float*)d_in[13];
    const float* k_mem    = (const float*)d_in[14];
    const float* w_conv   = (const float*)d_in[15];
    const float* w_memlin = (const float*)d_in[16];
    const float* b_memlin = (const float*)d_in[17];
    const float* w_fx     = (const float*)d_in[18];
    const float* b_fx     = (const float*)d_in[19];
    const float* gamma    = (const float*)d_in[20];
    const float* beta     = (const float*)d_in[21];
    float* out = (float*)d_out;

    int M = in_sizes[0] / 64;   // 50000
    int E = in_sizes[1] / 2;    // 800000

    int mb = (M + 63) / 64;     // row-tile blocks (782)
    int wb = (M + 7) / 8;       // warp-per-row blocks (256 thr = 8 warps)
    int nb = (M + 1023) / 1024; // scan chunks (49)

    // CSR build + zero pool accumulator
    zero_k<<<(M + 255) / 256, 256>>>(M);
    count_k<<<(E + 255) / 256, 256>>>(ei, E);
    scan1_k<<<nb, 1024>>>(M);
    scan2_k<<<1, 64>>>(nb);
    scan3_k<<<(M + 255) / 256, 256>>>(M);
    scatter_k<<<(E + 255) / 256, 256>>>(ei, E);

    // Layer 1
    gemm_ep1_k<<<dim3(1, mb), 256>>>(x, w_proj1, b_proj1, t1, M);
    agg1_k<<<wb, 256>>>(M);
    gemm_l1_k<<<dim3(1, mb), 256>>>(x, w_l1, b_l1, w_r1, M);   // fused norm+relu

    // Layer 2
    gemm_ep2_k<<<dim3(1, mb), 256>>>(w_proj2, b_proj2, t2, M);
    agg2_k<<<wb, 256>>>(M);
    gemm_l2_k<<<dim3(1, mb), 256>>>(w_l2, b_l2, w_r2, M);      // fused norm+relu

    // MemPooling + head
    pool_k<<<512, 256>>>(k_mem, w_conv, M);
    final_k<<<1, 128>>>(w_memlin, b_memlin, w_fx, b_fx, gamma, beta, out);
}